// round 17
// baseline (speedup 1.0000x reference)
#include <cuda_runtime.h>
#include <cuda_fp16.h>
#include <cstdint>

#define IN_F   4096
#define OUT_F  11008
#define M_TOT  512
#define BM     256
#define BN     128
#define BK     64
#define KHALF  2048
#define NCHUNK (KHALF / BK)     // 32
#define NTHREADS 320            // 8 consumer warps + 2 producer warps
#define NSTAGE 3
#define STAGE_SZ 49152          // A 32KB + B 16KB
static constexpr int SMEM_BYTES = NSTAGE * STAGE_SZ;   // 144 KB

// x converted to fp16 once per launch (scratch: __device__ global, no allocs)
__device__ __align__(16) __half g_xh[M_TOT * IN_F];
// kh=1 partial results (unique writer per element -> deterministic)
__device__ __align__(16) float g_p1[(size_t)M_TOT * OUT_F];

// ---------------- helpers ----------------
__device__ __forceinline__ uint32_t smem_u32(const void* p) {
    uint32_t a;
    asm("{ .reg .u64 t; cvta.to.shared.u64 t, %1; cvt.u32.u64 %0, t; }" : "=r"(a) : "l"(p));
    return a;
}

#define LDSM4(r0, r1, r2, r3, addr) \
    asm volatile("ldmatrix.sync.aligned.m8n8.x4.shared.b16 {%0,%1,%2,%3}, [%4];" \
        : "=r"(r0), "=r"(r1), "=r"(r2), "=r"(r3) : "r"(addr))

#define MMA16816(c, a, b0, b1) \
    asm volatile("mma.sync.aligned.m16n8k16.row.col.f32.f16.f16.f32 " \
        "{%0,%1,%2,%3}, {%4,%5,%6,%7}, {%8,%9}, {%0,%1,%2,%3};" \
        : "+f"((c)[0]), "+f"((c)[1]), "+f"((c)[2]), "+f"((c)[3]) \
        : "r"((a)[0]), "r"((a)[1]), "r"((a)[2]), "r"((a)[3]), "r"(b0), "r"(b1))

#define CP_ASYNC16(dst, src) \
    asm volatile("cp.async.cg.shared.global [%0], [%1], 16;" :: "r"(dst), "l"(src) : "memory")
#define CP_ASYNC_COMMIT() asm volatile("cp.async.commit_group;" ::: "memory")
#define CP_ASYNC_WAIT0()  asm volatile("cp.async.wait_group 0;" ::: "memory")

#define BAR_SYNC(id)   asm volatile("bar.sync %0, %1;"   :: "r"(id), "n"(NTHREADS) : "memory")
#define BAR_ARRIVE(id) asm volatile("bar.arrive %0, %1;" :: "r"(id), "n"(NTHREADS) : "memory")

__device__ __forceinline__ void sts128(uint32_t addr, uint4 v) {
    asm volatile("st.shared.v4.b32 [%0], {%1, %2, %3, %4};"
        :: "r"(addr), "r"(v.x), "r"(v.y), "r"(v.z), "r"(v.w) : "memory");
}

// dequant two int4-codes (stored as int32) -> packed fp16x2
__device__ __forceinline__ uint32_t packw(uint32_t q0, uint32_t q1, float s, float bz) {
    float f0 = fmaf((float)(int)q0, s, bz);
    float f1 = fmaf((float)(int)q1, s, bz);
    __half2 h = __floats2half2_rn(f0, f1);
    return *reinterpret_cast<uint32_t*>(&h);
}

// ---------------- kernel 1: x fp32 -> fp16 ----------------
__global__ void convert_x_kernel(const float* __restrict__ x) {
    int i = blockIdx.x * blockDim.x + threadIdx.x;
    float4 v = reinterpret_cast<const float4*>(x)[i];
    __half2 a = __floats2half2_rn(v.x, v.y);
    __half2 b = __floats2half2_rn(v.z, v.w);
    uint2 u;
    u.x = *reinterpret_cast<uint32_t*>(&a);
    u.y = *reinterpret_cast<uint32_t*>(&b);
    reinterpret_cast<uint2*>(g_xh)[i] = u;
}

// ---------------- kernel 3: out = out + g_p1 + bias (float4) --------------
__global__ void combine_kernel(float* __restrict__ out, const float* __restrict__ bias) {
    const size_t i = (size_t)blockIdx.x * blockDim.x + threadIdx.x;  // float4 idx
    float4 o = reinterpret_cast<float4*>(out)[i];
    const float4 p = reinterpret_cast<const float4*>(g_p1)[i];
    const float4 b = reinterpret_cast<const float4*>(bias)[i % (OUT_F / 4)];
    o.x += p.x + b.x;
    o.y += p.y + b.y;
    o.z += p.z + b.z;
    o.w += p.w + b.w;
    reinterpret_cast<float4*>(out)[i] = o;
}

// ---------------- kernel 2: warp-specialized dequant + HMMA GEMM ----------
// Stage layout (per stage, 48KB):
//   A: 256 rows x 64 fp16 (128B/row, SW128) at +0      (32 KB)
//   B: 128 rows x 64 fp16 (128B/row, SW128) at +32768  (16 KB)
// Producers (warps 8-9) fill stage kc%3; consumers (warps 0-7) drain.
// Named barriers: full[s] = 1+s (64 arrive + 256 sync),
//                 empty[s] = 4+s (256 arrive + 64 sync), count = 320.
__global__ __launch_bounds__(NTHREADS, 1)
void qlin_main_kernel(const int* __restrict__ qw,
                      const float* __restrict__ wsc,
                      const float* __restrict__ wzp,
                      float* __restrict__ out) {
    extern __shared__ __align__(1024) char smem[];
    const uint32_t sb = smem_u32(smem);
    const int tid  = threadIdx.x;
    const int lane = tid & 31;
    const int wid  = tid >> 5;
    const int m0 = blockIdx.x * BM;   // 2 M-tiles
    const int n0 = blockIdx.y * BN;   // 86 N-tiles
    const int kh = blockIdx.z;        // 2 K-splits
    const int kbase = kh * KHALF;

    if (wid < 8) {
        // ================= CONSUMERS =================
        const int mwarp = wid & 3;    // 4 M-warps (64 rows each)
        const int nwarp = wid >> 2;   // 2 N-warps (64 cols each)
        const int rA = lane & 15;
        const int cA = lane >> 4;
        const int rB = (lane & 7) | (((lane >> 4) & 1) << 3);
        const int cB = (lane >> 3) & 1;
        uint32_t baseA[4], baseB[4];
        #pragma unroll
        for (int i = 0; i < 4; ++i) {
            const int row = mwarp * 64 + i * 16 + rA;
            baseA[i] = (uint32_t)(row * 128 + ((cA << 4) ^ ((row & 7) << 4)));
        }
        #pragma unroll
        for (int jj = 0; jj < 4; ++jj) {
            const int row = nwarp * 64 + jj * 16 + rB;
            baseB[jj] = (uint32_t)(32768 + row * 128 + ((cB << 4) ^ ((row & 7) << 4)));
        }

        float acc[4][8][4];
        #pragma unroll
        for (int i = 0; i < 4; ++i)
            #pragma unroll
            for (int j = 0; j < 8; ++j)
                #pragma unroll
                for (int c = 0; c < 4; ++c) acc[i][j][c] = 0.f;

        for (int kc = 0; kc < NCHUNK; ++kc) {
            const int s = kc % NSTAGE;
            BAR_SYNC(1 + s);
            const uint32_t stage = sb + (uint32_t)(s * STAGE_SZ);
            #pragma unroll
            for (int ks = 0; ks < 4; ++ks) {
                const uint32_t ax = (uint32_t)(ks << 5);
                uint32_t a[4][4];
                #pragma unroll
                for (int i = 0; i < 4; ++i)
                    LDSM4(a[i][0], a[i][1], a[i][2], a[i][3], (stage + baseA[i]) ^ ax);
                #pragma unroll
                for (int jj = 0; jj < 4; ++jj) {
                    uint32_t r0, r1, r2, r3;
                    LDSM4(r0, r1, r2, r3, (stage + baseB[jj]) ^ ax);
                    #pragma unroll
                    for (int i = 0; i < 4; ++i) {
                        MMA16816(acc[i][2 * jj], a[i], r0, r1);
                        MMA16816(acc[i][2 * jj + 1], a[i], r2, r3);
                    }
                }
            }
            BAR_ARRIVE(4 + s);
        }

        // epilogue: plain coalesced float2 stores (unique writer per element)
        float* dst = (kh == 0) ? out : g_p1;
        const int r_base = m0 + mwarp * 64 + (lane >> 2);
        #pragma unroll
        for (int j = 0; j < 8; ++j) {
            const int col = n0 + nwarp * 64 + j * 8 + (lane & 3) * 2;
            #pragma unroll
            for (int i = 0; i < 4; ++i) {
                const int r0 = r_base + i * 16;
                *reinterpret_cast<float2*>(&dst[(size_t)r0 * OUT_F + col]) =
                    make_float2(acc[i][j][0], acc[i][j][1]);
                *reinterpret_cast<float2*>(&dst[(size_t)(r0 + 8) * OUT_F + col]) =
                    make_float2(acc[i][j][2], acc[i][j][3]);
            }
        }
    } else {
        // ================= PRODUCERS (2 warps, 64 threads) =================
        const int ptid = tid - 256;   // 0..63
        const int rgrp = ptid >> 3;   // 0..7
        const int kp   = ptid & 7;    // 0..7

        // B codes: 8 threads/row, 8 codes (32B) each; rows t*8+rgrp, t=0..15
        const int* bsrc = qw + (size_t)(n0 + rgrp) * IN_F + kbase + kp * 8;
        float s_[16], bz_[16];
        uint4 qa[4], qb[4];           // depth-4 software pipeline

        for (int kc = 0; kc < NCHUNK; ++kc) {
            const int s = kc % NSTAGE;
            if (kc >= NSTAGE) BAR_SYNC(4 + s);
            const uint32_t stage = sb + (uint32_t)(s * STAGE_SZ);

            // refresh scales every 2 chunks (group = 128 K)
            if ((kc & 1) == 0) {
                const int g = (kbase >> 7) + (kc >> 1);
                #pragma unroll
                for (int t = 0; t < 16; ++t) {
                    const int row = n0 + t * 8 + rgrp;
                    const float sv = wsc[row * 32 + g];
                    s_[t]  = sv;
                    bz_[t] = -wzp[row * 32 + g] * sv;
                }
            }

            // A tile via cp.async: 256 rows, 32 x 16B per thread
            #pragma unroll
            for (int t = 0; t < 32; ++t) {
                const int row = t * 8 + rgrp;
                const __half* src = g_xh + (size_t)(m0 + row) * IN_F + kbase + kc * BK + kp * 8;
                const uint32_t dst = stage + (uint32_t)(row * 128)
                                   + (uint32_t)((kp << 4) ^ ((rgrp) << 4));
                CP_ASYNC16(dst, src);
            }
            CP_ASYNC_COMMIT();

            // B codes: 128 rows (t=0..15), pipelined LDG -> dequant -> STS
            #pragma unroll
            for (int t = 0; t < 4; ++t) {
                const int* p = bsrc + (size_t)(t * 8) * IN_F + kc * BK;
                qa[t] = *reinterpret_cast<const uint4*>(p);
                qb[t] = *reinterpret_cast<const uint4*>(p + 4);
            }
            #pragma unroll
            for (int t = 0; t < 16; ++t) {
                const uint4 a = qa[t & 3];
                const uint4 b = qb[t & 3];
                if (t + 4 < 16) {
                    const int* p = bsrc + (size_t)((t + 4) * 8) * IN_F + kc * BK;
                    qa[t & 3] = *reinterpret_cast<const uint4*>(p);
                    qb[t & 3] = *reinterpret_cast<const uint4*>(p + 4);
                }
                uint4 h;
                h.x = packw(a.x, a.y, s_[t], bz_[t]);
                h.y = packw(a.z, a.w, s_[t], bz_[t]);
                h.z = packw(b.x, b.y, s_[t], bz_[t]);
                h.w = packw(b.z, b.w, s_[t], bz_[t]);
                const int row = t * 8 + rgrp;
                sts128(stage + 32768u + (uint32_t)(row * 128)
                       + (uint32_t)((kp << 4) ^ ((rgrp) << 4)), h);
            }

            CP_ASYNC_WAIT0();
            BAR_ARRIVE(1 + s);
        }
    }
}

// ---------------- launch ----------------
extern "C" void kernel_launch(void* const* d_in, const int* in_sizes, int n_in,
                              void* d_out, int out_size) {
    (void)in_sizes; (void)n_in; (void)out_size;
    const float* x    = (const float*)d_in[0];
    const int*   qw   = (const int*)d_in[1];
    const float* wsc  = (const float*)d_in[2];
    const float* wzp  = (const float*)d_in[3];
    const float* bias = (const float*)d_in[4];
    float* out = (float*)d_out;

    cudaFuncSetAttribute(qlin_main_kernel,
                         cudaFuncAttributeMaxDynamicSharedMemorySize, SMEM_BYTES);

    convert_x_kernel<<<2048, 256>>>(x);
    qlin_main_kernel<<<dim3(2, 86, 2), NTHREADS, SMEM_BYTES>>>(qw, wsc, wzp, out);
    // 512*11008/4 float4 elems = 1,409,024 ; /256 = 5504 blocks (exact)
    combine_kernel<<<5504, 256>>>(out, bias);
}